// round 16
// baseline (speedup 1.0000x reference)
#include <cuda_runtime.h>
#include <cuda_bf16.h>

#define WARPS_PER_BLOCK 8
#define THREADS 256

typedef unsigned long long u64;

__host__ __device__ constexpr int msbbit(int v) { int b = 1; while (v >>= 1) b <<= 1; return b; }

__device__ __forceinline__ u64 pk(float lo, float hi) {
    u64 r; asm("mov.b64 %0, {%1, %2};" : "=l"(r) : "f"(lo), "f"(hi)); return r;
}
__device__ __forceinline__ u64 pkb(float v) {
    u64 r; asm("mov.b64 %0, {%1, %1};" : "=l"(r) : "f"(v)); return r;
}
__device__ __forceinline__ void upk(u64 v, float& lo, float& hi) {
    asm("mov.b64 {%0, %1}, %2;" : "=f"(lo), "=f"(hi) : "l"(v));
}
__device__ __forceinline__ u64 swap64(u64 v) {
    u64 r;
    asm("{ .reg .b32 lo, hi; mov.b64 {lo, hi}, %1; mov.b64 %0, {hi, lo}; }"
        : "=l"(r) : "l"(v));
    return r;
}
__device__ __forceinline__ u64 fma2(u64 a, u64 b, u64 c) {
    u64 r; asm("fma.rn.f32x2 %0, %1, %2, %3;" : "=l"(r) : "l"(a), "l"(b), "l"(c)); return r;
}
__device__ __forceinline__ u64 mul2(u64 a, u64 b) {
    u64 r; asm("mul.rn.f32x2 %0, %1, %2;" : "=l"(r) : "l"(a), "l"(b)); return r;
}
__device__ __forceinline__ u64 neg64(u64 v) { return v ^ 0x8000000080000000ULL; }

// packed complex state value v = (re, im).
// complex multiply by (br, bi): v = BR*v + BI*swap(v), BR=(br,br), BI=(-bi,bi)
__device__ __forceinline__ void cmulp(u64& v, u64 BR, u64 BI) {
    v = fma2(BR, v, mul2(BI, swap64(v)));
}

// Real Ry gate on logical bit p, frame coords (lane 5b, reg 4b); V[j] = (re,im).
// MASK low4 = reg pairing, high5 = lane pairing; ROLE = side mask.
// side0 row = (ct, -st), side1 row = (ct, +st).
template<int MASK, int ROLE>
__device__ __forceinline__ void gate_y(u64 (&V)[16], float ct, float st, int lane) {
    constexpr int ml = MASK & 0xF;
    constexpr int mw = (MASK >> 4) & 0x1F;
    const int lp = __popc((ROLE >> 4) & lane) & 1;
    const float base = lp ? st : -st;          // partner coeff for reg-parity 0
    const u64 C  = pkb(ct);
    const u64 S0 = pkb(base);
    const u64 S1 = neg64(S0);

    if constexpr (mw == 0) {
        constexpr int hb = msbbit(ml);
        #pragma unroll
        for (int j = 0; j < 16; ++j) {
            if ((j & hb) != 0) continue;
            const int k = j ^ ml;
            const u64 Sj = (__popc(ROLE & j) & 1) ? S1 : S0;
            const u64 Sk = (__popc(ROLE & k) & 1) ? S1 : S0;
            const u64 nj = fma2(C, V[j], mul2(Sj, V[k]));
            const u64 nk = fma2(C, V[k], mul2(Sk, V[j]));
            V[j] = nj; V[k] = nk;
        }
    } else if constexpr (ml == 0) {
        #pragma unroll
        for (int j = 0; j < 16; ++j) {
            const u64 p = __shfl_xor_sync(0xffffffffu, V[j], mw);
            const u64 Sj = (__popc(ROLE & j) & 1) ? S1 : S0;
            V[j] = fma2(C, V[j], mul2(Sj, p));
        }
    } else {
        constexpr int hb = msbbit(ml);
        #pragma unroll
        for (int j = 0; j < 16; ++j) {
            if ((j & hb) != 0) continue;
            const int k = j ^ ml;
            const u64 pj = __shfl_xor_sync(0xffffffffu, V[k], mw);
            const u64 pk_ = __shfl_xor_sync(0xffffffffu, V[j], mw);
            const u64 Sj = (__popc(ROLE & j) & 1) ? S1 : S0;
            const u64 Sk = (__popc(ROLE & k) & 1) ? S1 : S0;
            V[j] = fma2(C, V[j], mul2(Sj, pj));
            V[k] = fma2(C, V[k], mul2(Sk, pk_));
        }
    }
}

// Fused commuting L2 Ry pair sharing lane mask 0x1E:
//   A = (MASK 0x1E1, ROLE 0x065), B = (MASK 0x1E0, ROLE 0x095).
// out(u) = cAcB in(u) + sA(u) in(u^0x1E1) + sB(u) in(u^0x1E0) + sAB(lane) in(u^1).
__device__ __forceinline__ void gate_fused_1E(u64 (&V)[16],
                                              float cA, float stA, float cB, float stB,
                                              int lane) {
    const int lpA  = __popc(0x06 & lane) & 1;
    const int lpB  = __popc(0x09 & lane) & 1;
    const int lpAB = __popc(0x0F & lane) & 1;
    const float cc     = cA * cB;
    const float baseA  = (lpA ? stA : -stA) * cB;
    const float baseB  = (lpB ? stB : -stB) * cA;
    const float baseAB = lpAB ? -(stA * stB) : (stA * stB);
    const u64 KC  = pkb(cc);
    const u64 KA0 = pkb(baseA), KA1 = neg64(KA0);
    const u64 KB0 = pkb(baseB), KB1 = neg64(KB0);
    const u64 KAB = pkb(baseAB);

    #pragma unroll
    for (int j = 0; j < 16; j += 2) {
        const int k = j + 1;
        const u64 sj = V[j], sk = V[k];
        const u64 pj = __shfl_xor_sync(0xffffffffu, sj, 0x1E);
        const u64 pk_ = __shfl_xor_sync(0xffffffffu, sk, 0x1E);
        const bool Tj = (__popc(5 & j) & 1) != 0;
        const u64 SAj = Tj ? KA1 : KA0, SAk = Tj ? KA0 : KA1;
        const u64 SBj = Tj ? KB1 : KB0, SBk = Tj ? KB0 : KB1;
        V[j] = fma2(KC, sj, fma2(SAj, pk_, fma2(SBj, pj, mul2(KAB, sk))));
        V[k] = fma2(KC, sk, fma2(SAk, pj, fma2(SBk, pk_, mul2(KAB, sj))));
    }
}

// state *= unit-modulus diagonal; smem holds prebuilt packs DR=(c,c), DI=(-s,s)
__device__ __forceinline__ void apply_diag(u64 (&V)[16],
                                           const u64 (*__restrict__ DR)[32],
                                           const u64 (*__restrict__ DI)[32], int lane) {
    #pragma unroll
    for (int j = 0; j < 16; ++j) {
        cmulp(V[j], DR[j][lane], DI[j][lane]);
    }
}

__device__ __forceinline__ float laneWHT(float v, unsigned s0, unsigned s1, unsigned s2,
                                         unsigned s3, unsigned s4) {
    float t;
    t = __shfl_xor_sync(0xffffffffu, v, 1);  v = t + __uint_as_float(__float_as_uint(v) ^ s0);
    t = __shfl_xor_sync(0xffffffffu, v, 2);  v = t + __uint_as_float(__float_as_uint(v) ^ s1);
    t = __shfl_xor_sync(0xffffffffu, v, 4);  v = t + __uint_as_float(__float_as_uint(v) ^ s2);
    t = __shfl_xor_sync(0xffffffffu, v, 8);  v = t + __uint_as_float(__float_as_uint(v) ^ s3);
    t = __shfl_xor_sync(0xffffffffu, v, 16); v = t + __uint_as_float(__float_as_uint(v) ^ s4);
    return v;
}

// Frame: slot s = j0*0x003 ^ j1*0x006 ^ j2*0x00C ^ j3*0x018
//              ^ l0*0x001 ^ l1*0x020 ^ l2*0x040 ^ l3*0x080 ^ l4*0x100
__device__ __forceinline__ int slot_of(int ln, int j) {
    int s = 0;
    if (j & 1)  s ^= 0x003;
    if (j & 2)  s ^= 0x006;
    if (j & 4)  s ^= 0x00C;
    if (j & 8)  s ^= 0x018;
    if (ln & 1)  s ^= 0x001;
    if (ln & 2)  s ^= 0x020;
    if (ln & 4)  s ^= 0x040;
    if (ln & 8)  s ^= 0x080;
    if (ln & 16) s ^= 0x100;
    return s;
}

__global__ void __launch_bounds__(THREADS, 3)
qlayer_kernel(const float* __restrict__ x, const float* __restrict__ wts,
              float* __restrict__ out, int nsamp) {
    __shared__ float sw[81];
    __shared__ __align__(16) float s_m0[9][4];   // layer-0 matrices
    __shared__ float s_y[2][9][2];               // layers 1,2 Ry coeffs {ct, st}
    __shared__ u64 sDR[2][16][32];               // diag packs (c,c)
    __shared__ u64 sDI[2][16][32];               // diag packs (-s,s)
    __shared__ __align__(16) float4 s_init[WARPS_PER_BLOCK][9];

    const int tid = threadIdx.x;
    if (tid < 81) sw[tid] = wts[tid];
    __syncthreads();

    if (tid < 9) {
        const int qb = tid;
        const float phi = sw[qb * 3 + 0];
        const float th  = sw[qb * 3 + 1];
        const float om  = sw[qb * 3 + 2];
        float st, ct; sincosf(0.5f * th, &st, &ct);
        float sA, cA; sincosf(0.5f * (phi + om), &sA, &cA);
        float sB, cB; sincosf(0.5f * (phi - om), &sB, &cB);
        s_m0[qb][0] =  cA * ct;
        s_m0[qb][1] = -sA * ct;
        s_m0[qb][2] = -cB * st;
        s_m0[qb][3] = -sB * st;
    }
    if (tid < 18) {
        const int l = tid / 9 + 1, qb = tid % 9;
        float st, ct; sincosf(0.5f * sw[(l * 9 + qb) * 3 + 1], &st, &ct);
        s_y[l - 1][qb][0] = ct;
        s_y[l - 1][qb][1] = st;
    }
    {
        // D_A = Z(phi1)^{P1}; D_B = Z(om1)^{P1} * Z(phi2)^{P2}.
        constexpr int R1[9] = {0x1FF,0x1FE,0x1FC,0x1F8,0x1F0,0x1E0,0x1C0,0x180,0x0FF};
        constexpr int R2[9] = {0x0CC,0x066,0x133,0x198,0x0CF,0x060,0x13F,0x14C,0x099};
        #pragma unroll
        for (int t = 0; t < 2; ++t) {
            const int idx = tid + t * 256;        // 512 (j,lane) pairs
            const int j = idx >> 5, ln = idx & 31;
            const int s = slot_of(ln, j);
            float thA = 0.f, thB = 0.f;
            #pragma unroll
            for (int p = 0; p < 9; ++p) {
                const int q = 8 - p;
                const float f1 = sw[(9 + q) * 3 + 0];
                const float o1 = sw[(9 + q) * 3 + 2];
                const float f2 = sw[(18 + q) * 3 + 0];
                const float g1 = (__popc(R1[p] & s) & 1) ? 0.5f : -0.5f;
                const float g2 = (__popc(R2[p] & s) & 1) ? 0.5f : -0.5f;
                thA += g1 * f1;
                thB += g1 * o1 + g2 * f2;
            }
            float ca, sa, cb, sb;
            sincosf(thA, &sa, &ca);
            sincosf(thB, &sb, &cb);
            sDR[0][j][ln] = pkb(ca); sDI[0][j][ln] = pk(-sa, sa);
            sDR[1][j][ln] = pkb(cb); sDI[1][j][ln] = pk(-sb, sb);
        }
    }
    __syncthreads();

    const int lane = tid & 31;
    const int warp = tid >> 5;
    const int b = blockIdx.x * WARPS_PER_BLOCK + warp;
    if (b >= nsamp) return;

    // --- init vectors: lanes 0-8 compute, stage via smem ---
    if (lane < 9) {
        const float xv = x[b * 9 + lane];
        float sx, cx; sincosf(0.5f * xv, &sx, &cx);
        const float4 m = *reinterpret_cast<const float4*>(s_m0[lane]);
        float4 v;
        v.x =  m.x * cx + m.w * sx;   // w0r
        v.y =  m.y * cx - m.z * sx;   // w0i
        v.z = -m.z * cx - m.y * sx;   // w1r
        v.w =  m.w * cx - m.x * sx;   // w1i
        s_init[warp][lane] = v;
    }
    __syncwarp();

    const int l0 = lane & 1, l1 = (lane >> 1) & 1, l2 = (lane >> 2) & 1;
    const int l3 = (lane >> 3) & 1, l4 = (lane >> 4) & 1;

    // --- packed product state, V[j] = (re, im) of slot (lane, j) ---
    // factors: p0:w8[j0^l0] p1:w7[j0^j1] p2:w6[j1^j2] p3:w5[j2^j3] p4:w4[j3]
    //          p5:w3[l1] p6:w2[l2] p7:w1[l3] p8:w0[l4]
    u64 V[16];
    {
        // factor packs per qubit: value pack (br,bi) + cmulp coeff packs (br,br), (-bi,bi)
        float4 f;
        // lane-selected head (qubits 0..3)
        f = s_init[warp][0];
        u64 B = l4 ? pk(f.z, f.w) : pk(f.x, f.y);
        f = s_init[warp][1];
        cmulp(B, l3 ? pkb(f.z) : pkb(f.x), l3 ? pk(-f.w, f.w) : pk(-f.y, f.y));
        f = s_init[warp][2];
        cmulp(B, l2 ? pkb(f.z) : pkb(f.x), l2 ? pk(-f.w, f.w) : pk(-f.y, f.y));
        f = s_init[warp][3];
        cmulp(B, l1 ? pkb(f.z) : pkb(f.x), l1 ? pk(-f.w, f.w) : pk(-f.y, f.y));

        f = s_init[warp][4];
        const u64 Q4R[2] = { pkb(f.x), pkb(f.z) };
        const u64 Q4I[2] = { pk(-f.y, f.y), pk(-f.w, f.w) };
        f = s_init[warp][5];
        const u64 Q5R[2] = { pkb(f.x), pkb(f.z) };
        const u64 Q5I[2] = { pk(-f.y, f.y), pk(-f.w, f.w) };
        f = s_init[warp][6];
        const u64 Q6R[2] = { pkb(f.x), pkb(f.z) };
        const u64 Q6I[2] = { pk(-f.y, f.y), pk(-f.w, f.w) };
        f = s_init[warp][7];
        const u64 Q7R[2] = { pkb(f.x), pkb(f.z) };
        const u64 Q7I[2] = { pk(-f.y, f.y), pk(-f.w, f.w) };
        f = s_init[warp][8];
        // qubit 8 selected by s0 = j0 ^ l0
        const u64 Q8R[2] = { pkb(l0 ? f.z : f.x), pkb(l0 ? f.x : f.z) };   // index j0
        const u64 Q8I[2] = { l0 ? pk(-f.w, f.w) : pk(-f.y, f.y),
                             l0 ? pk(-f.y, f.y) : pk(-f.w, f.w) };

        u64 t1[2];
        #pragma unroll
        for (int e3 = 0; e3 < 2; ++e3) {
            t1[e3] = B; cmulp(t1[e3], Q4R[e3], Q4I[e3]);
        }
        u64 t2[4];
        #pragma unroll
        for (int t = 0; t < 4; ++t) {
            const int e2 = t & 1, e3 = t >> 1;
            const int s3 = e2 ^ e3;
            t2[t] = t1[e3]; cmulp(t2[t], Q5R[s3], Q5I[s3]);
        }
        u64 t3[8];
        #pragma unroll
        for (int h = 0; h < 8; ++h) {
            const int e1 = h & 1, e2 = (h >> 1) & 1;
            const int s2 = e1 ^ e2;
            t3[h] = t2[h >> 1]; cmulp(t3[h], Q6R[s2], Q6I[s2]);
        }
        #pragma unroll
        for (int j = 0; j < 16; ++j) {
            const int j0 = j & 1, e1 = (j >> 1) & 1;
            const int s1 = j0 ^ e1;
            V[j] = t3[j >> 1];
            cmulp(V[j], Q7R[s1], Q7I[s1]);
            cmulp(V[j], Q8R[j0], Q8I[j0]);
        }
    }

    // --- D_A ---
    apply_diag(V, sDR[0], sDI[0], lane);

    // --- layer-1 Ry gates ---
    gate_y<0x190, 0x1F0>(V, s_y[0][8][0], s_y[0][8][1], lane);  // p=0
    gate_y<0x001, 0x1E1>(V, s_y[0][7][0], s_y[0][7][1], lane);  // p=1
    gate_y<0x002, 0x1E2>(V, s_y[0][6][0], s_y[0][6][1], lane);  // p=2
    gate_y<0x004, 0x1E4>(V, s_y[0][5][0], s_y[0][5][1], lane);  // p=3
    gate_y<0x008, 0x1E8>(V, s_y[0][4][0], s_y[0][4][1], lane);  // p=4
    gate_y<0x03F, 0x1E0>(V, s_y[0][3][0], s_y[0][3][1], lane);  // p=5
    gate_y<0x060, 0x1C0>(V, s_y[0][2][0], s_y[0][2][1], lane);  // p=6
    gate_y<0x0C0, 0x180>(V, s_y[0][1][0], s_y[0][1][1], lane);  // p=7
    gate_y<0x180, 0x0F0>(V, s_y[0][0][0], s_y[0][0][1], lane);  // p=8

    // --- D_B ---
    apply_diag(V, sDR[1], sDI[1], lane);

    // --- layer-2 Ry gates ---  [Z(om2) dropped: pure phase before |.|^2]
    gate_y<0x16F, 0x0CA>(V, s_y[1][8][0], s_y[1][8][1], lane);  // p=0
    gate_fused_1E(V, s_y[1][7][0], s_y[1][7][1],
                     s_y[1][0][0], s_y[1][0][1], lane);          // p=1 + p=8
    gate_y<0x192, 0x13A>(V, s_y[1][6][0], s_y[1][6][1], lane);  // p=2
    gate_y<0x005, 0x184>(V, s_y[1][5][0], s_y[1][5][1], lane);  // p=3
    gate_y<0x00A, 0x0D8>(V, s_y[1][4][0], s_y[1][4][1], lane);  // p=4
    gate_y<0x03B, 0x060>(V, s_y[1][3][0], s_y[1][3][1], lane);  // p=5
    gate_y<0x068, 0x130>(V, s_y[1][2][0], s_y[1][2][1], lane);  // p=6
    gate_y<0x0FF, 0x14A>(V, s_y[1][1][0], s_y[1][1][1], lane);  // p=7

    // --- probabilities (scalar), register-side WHT over j ---
    float prob[16];
    #pragma unroll
    for (int j = 0; j < 16; ++j) {
        const u64 m = mul2(V[j], V[j]);
        float lo, hi; upk(m, lo, hi);
        prob[j] = lo + hi;
    }
    #pragma unroll
    for (int bb = 0; bb < 4; ++bb) {
        const int mk = 1 << bb;
        #pragma unroll
        for (int j = 0; j < 16; ++j) {
            if ((j & mk) != 0) continue;
            const float u = prob[j], v = prob[j | mk];
            prob[j] = u + v; prob[j | mk] = u - v;
        }
    }

    // --- lane-side WHTs; picks = coord Walsh indices ---
    const unsigned sg0 = (unsigned)( lane       & 1) << 31;
    const unsigned sg1 = (unsigned)((lane >> 1) & 1) << 31;
    const unsigned sg2 = (unsigned)((lane >> 2) & 1) << 31;
    const unsigned sg3 = (unsigned)((lane >> 3) & 1) << 31;
    const unsigned sg4 = (unsigned)((lane >> 4) & 1) << 31;
    const float SA = laneWHT(prob[0xA], sg0, sg1, sg2, sg3, sg4);
    const float SD = laneWHT(prob[0xD], sg0, sg1, sg2, sg3, sg4);
    const float SE = laneWHT(prob[0xE], sg0, sg1, sg2, sg3, sg4);
    const float S5 = laneWHT(prob[0x5], sg0, sg1, sg2, sg3, sg4);
    const float S2 = laneWHT(prob[0x2], sg0, sg1, sg2, sg3, sg4);
    const float S4 = laneWHT(prob[0x4], sg0, sg1, sg2, sg3, sg4);
    const float SF = laneWHT(prob[0xF], sg0, sg1, sg2, sg3, sg4);
    const float S7 = laneWHT(prob[0x7], sg0, sg1, sg2, sg3, sg4);

    const float r0 = __shfl_sync(0xffffffffu, SA, 0x15);
    const float r1 = __shfl_sync(0xffffffffu, SD, 0x0B);
    const float r2 = __shfl_sync(0xffffffffu, SE, 0x14);
    const float r3 = __shfl_sync(0xffffffffu, S5, 0x0F);
    const float r4 = __shfl_sync(0xffffffffu, S2, 0x19);
    const float r5 = __shfl_sync(0xffffffffu, S4, 0x0B);
    const float r6 = __shfl_sync(0xffffffffu, SF, 0x1C);
    const float r7 = __shfl_sync(0xffffffffu, S7, 0x1F);
    const float r8 = __shfl_sync(0xffffffffu, SE, 0x07);

    if (lane < 9) {
        float v = r0;
        if (lane == 1) v = r1;
        if (lane == 2) v = r2;
        if (lane == 3) v = r3;
        if (lane == 4) v = r4;
        if (lane == 5) v = r5;
        if (lane == 6) v = r6;
        if (lane == 7) v = r7;
        if (lane == 8) v = r8;
        out[b * 9 + lane] = v;
    }
}

extern "C" void kernel_launch(void* const* d_in, const int* in_sizes, int n_in,
                              void* d_out, int out_size) {
    const float* x   = (const float*)d_in[0];   // (32768, 9) float32
    const float* wts = (const float*)d_in[1];   // (3, 9, 3) float32
    float* out = (float*)d_out;                 // (32768, 9) float32
    const int nsamp = in_sizes[0] / 9;
    const int blocks = (nsamp + WARPS_PER_BLOCK - 1) / WARPS_PER_BLOCK;
    qlayer_kernel<<<blocks, THREADS>>>(x, wts, out, nsamp);
}